// round 14
// baseline (speedup 1.0000x reference)
#include <cuda_runtime.h>
#include <cstdint>

#define GRID1     296        // 148 SMs * 2 CTAs
#define NCONS     512        // consumer threads
#define NTHREADS  544        // + 1 producer warp
#define NSTAGES   5
#define CHUNK_E   1024       // elements per chunk/stage
#define X_BYTES   8192       // CHUNK_E * 8
#define D_BYTES   4096       // CHUNK_E * 4
#define TOT_BYTES 20480      // x + y + dist
#define STAGE_B   20480
#define SMEM_BUF  1024       // buffers start here; barriers in [0..80)
#define SMEM_DYN  (SMEM_BUF + NSTAGES * STAGE_B)   // 103424 B/CTA; x2 = 207KB/SM

__device__ float        g_partials[GRID1 * 8];
__device__ unsigned int g_ticket;     // zero-init; last block resets

struct Acc {
    float sm[4];
    unsigned long long cntp;          // 4 x 16-bit packed counts
};

__device__ __forceinline__ uint32_t smem_u32(const void* p) {
    uint32_t a;
    asm("{ .reg .u64 t; cvta.to.shared.u64 t, %1; cvt.u32.u64 %0, t; }"
        : "=r"(a) : "l"(p));
    return a;
}
__device__ __forceinline__ void mbar_init(uint32_t m, uint32_t cnt) {
    asm volatile("mbarrier.init.shared.b64 [%0], %1;" :: "r"(m), "r"(cnt) : "memory");
}
__device__ __forceinline__ void mbar_expect_tx(uint32_t m, uint32_t bytes) {
    asm volatile("mbarrier.arrive.expect_tx.shared.b64 _, [%0], %1;"
                 :: "r"(m), "r"(bytes) : "memory");
}
__device__ __forceinline__ void mbar_arrive(uint32_t m) {
    asm volatile("mbarrier.arrive.shared.b64 _, [%0];" :: "r"(m) : "memory");
}
__device__ __forceinline__ void mbar_wait(uint32_t m, uint32_t ph) {
    asm volatile(
        "{\n\t.reg .pred P1;\n\t"
        "W_%=:\n\t"
        "mbarrier.try_wait.parity.acquire.cta.shared::cta.b64 P1, [%0], %1, 0x989680;\n\t"
        "@P1 bra D_%=;\n\t"
        "bra W_%=;\n\t"
        "D_%=:\n\t}"
        :: "r"(m), "r"(ph) : "memory");
}
__device__ __forceinline__ void bulk_g2s(uint32_t dst, const void* src,
                                         uint32_t bytes, uint32_t mbar) {
    asm volatile(
        "cp.async.bulk.shared::cta.global.mbarrier::complete_tx::bytes [%0], [%1], %2, [%3];"
        :: "r"(dst), "l"(src), "r"(bytes), "r"(mbar) : "memory");
}

__device__ __forceinline__ void elem_acc(Acc& A, float a, float b,
                                         float c, float d, float dv)
{
    float u  = a - c;
    float v  = b - d;
    float d2 = fmaf(u, u, v * v);
    float x2 = fmaf(a, a, b * b);
    float y2 = fmaf(c, c, d * d);
    float p  = fmaxf(x2 * y2, 1e-30f);
    float s  = p * rsqrtf(p);                 // ~sqrt(x2*y2), one MUFU
    float a2 = x2 + y2 - 2.0f * s;            // (|x|-|y|)^2
    float m  = fmaf(0.2f, a2, d2);
    int ib = (int)(dv * 4.0f);
    ib = ib > 3 ? 3 : ib;
    A.cntp += 1ull << (ib << 4);
    #pragma unroll
    for (int bb = 0; bb < 4; bb++)
        if (bb == ib) A.sm[bb] += m;
}

__global__ __launch_bounds__(NTHREADS, 2)
void radial_tma(const float* __restrict__ x,
                const float* __restrict__ y,
                const float* __restrict__ dist,
                int n, float* __restrict__ out)
{
    extern __shared__ __align__(128) char smem[];
    const uint32_t sb  = smem_u32(smem);
    const int      tid = threadIdx.x;
    const int nchunks = n / CHUNK_E;

    // Barriers: full[s] = sb + s*16, empty[s] = sb + s*16 + 8.
    if (tid == 0) {
        #pragma unroll
        for (int s = 0; s < NSTAGES; s++) {
            mbar_init(sb + s * 16,     1);      // full (tx-based)
            mbar_init(sb + s * 16 + 8, NCONS);  // empty
        }
    }
    __syncthreads();

    Acc A;
    A.sm[0] = A.sm[1] = A.sm[2] = A.sm[3] = 0.f;
    A.cntp = 0ull;

    if (tid == NCONS) {
        // -------- producer (one elected thread; runs up to 4 stages ahead) ----
        int s = 0; unsigned ph = 1;            // fresh empties pass parity 1
        const char* xg = (const char*)x;
        const char* yg = (const char*)y;
        const char* dg = (const char*)dist;
        for (int c = blockIdx.x; c < nchunks; c += gridDim.x) {
            uint32_t full  = sb + s * 16;
            uint32_t empty = sb + s * 16 + 8;
            uint32_t buf   = sb + SMEM_BUF + s * STAGE_B;
            mbar_wait(empty, ph);
            mbar_expect_tx(full, TOT_BYTES);
            bulk_g2s(buf,               xg + (size_t)c * X_BYTES, X_BYTES, full);
            bulk_g2s(buf + X_BYTES,     yg + (size_t)c * X_BYTES, X_BYTES, full);
            bulk_g2s(buf + 2 * X_BYTES, dg + (size_t)c * D_BYTES, D_BYTES, full);
            if (++s == NSTAGES) { s = 0; ph ^= 1; }
        }
    } else if (tid < NCONS) {
        // -------- consumers (512 threads; 2 elements each per stage) --------
        int s = 0; unsigned ph = 0;
        for (int c = blockIdx.x; c < nchunks; c += gridDim.x) {
            uint32_t full  = sb + s * 16;
            uint32_t empty = sb + s * 16 + 8;
            char* buf = smem + SMEM_BUF + s * STAGE_B;
            mbar_wait(full, ph);
            const float4* xs  = (const float4*)(buf);
            const float4* ys  = (const float4*)(buf + X_BYTES);
            const float2* dsv = (const float2*)(buf + 2 * X_BYTES);
            float4 xv = xs[tid];
            float4 yv = ys[tid];
            float2 dv = dsv[tid];
            elem_acc(A, xv.x, xv.y, yv.x, yv.y, dv.x);
            elem_acc(A, xv.z, xv.w, yv.z, yv.w, dv.y);
            mbar_arrive(empty);
            if (++s == NSTAGES) { s = 0; ph ^= 1; }
        }
        // Generic tail (n % CHUNK_E) via direct loads — zero for this size.
        if (blockIdx.x == 0) {
            for (int e = nchunks * CHUNK_E + tid; e < n; e += NCONS)
                elem_acc(A, x[2 * e], x[2 * e + 1], y[2 * e], y[2 * e + 1], dist[e]);
        }
    }
    __syncthreads();

    // Block reduction of 8 values (producer warp contributes zeros).
    float v[8];
    #pragma unroll
    for (int b = 0; b < 4; b++) {
        v[b]     = A.sm[b];
        v[4 + b] = (float)((unsigned)(A.cntp >> (b << 4)) & 0xFFFFu);
    }
    __shared__ float shr[NTHREADS / 32][8];
    const int lane = tid & 31;
    const int wid  = tid >> 5;
    #pragma unroll
    for (int k = 0; k < 8; k++) {
        #pragma unroll
        for (int o = 16; o > 0; o >>= 1)
            v[k] += __shfl_down_sync(0xffffffffu, v[k], o);
    }
    if (lane == 0) {
        #pragma unroll
        for (int k = 0; k < 8; k++) shr[wid][k] = v[k];
    }
    __syncthreads();
    if (tid < 8) {
        float s = 0.f;
        #pragma unroll
        for (int w = 0; w < NTHREADS / 32; w++) s += shr[w][tid];
        g_partials[blockIdx.x * 8 + tid] = s;
    }

    // ---- last-block final reduction (threadfence + ticket) ----
    __shared__ int isLast;
    __threadfence();
    if (tid == 0) {
        unsigned t = atomicAdd(&g_ticket, 1u);
        isLast = (t == (unsigned)(gridDim.x - 1));
    }
    __syncthreads();
    if (!isLast) return;

    const int k  = tid & 7;
    const int r0 = tid >> 3;
    float acc = 0.f;
    for (int r = r0; r < GRID1; r += NTHREADS / 8)
        acc += g_partials[r * 8 + k];

    __shared__ float sh2[NTHREADS];
    __shared__ float fin[8];
    sh2[tid] = acc;
    __syncthreads();
    if (tid < 8) {
        float s = 0.f;
        #pragma unroll
        for (int j = 0; j < NTHREADS / 8; j++) s += sh2[j * 8 + tid];
        fin[tid] = s;
    }
    __syncthreads();
    if (tid == 0) {
        float loss = 0.f;
        #pragma unroll
        for (int b = 0; b < 4; b++) {
            float cc = fin[4 + b];
            if (cc > 0.f) loss += fin[b] / (2.0f * cc);
        }
        out[0] = loss;
        g_ticket = 0u;                          // reset for next replay
    }
}

extern "C" void kernel_launch(void* const* d_in, const int* in_sizes, int n_in,
                              void* d_out, int out_size)
{
    const float* x    = (const float*)d_in[0];   // [N,2] f32
    const float* y    = (const float*)d_in[1];   // [N,2] f32
    const float* dist = (const float*)d_in[2];   // [N]   f32
    const int n = in_sizes[2];

    cudaFuncSetAttribute(radial_tma,
                         cudaFuncAttributeMaxDynamicSharedMemorySize, SMEM_DYN);
    radial_tma<<<GRID1, NTHREADS, SMEM_DYN>>>(x, y, dist, n, (float*)d_out);
}

// round 15
// speedup vs baseline: 1.0670x; 1.0670x over previous
#include <cuda_runtime.h>
#include <cstdint>

#define GRID1     296        // 148 SMs * 2 CTAs
#define NCONS     512        // consumer threads
#define NTHREADS  544        // + 1 producer warp
#define NSTAGES   4
#define CHUNK_E   1024       // elements per chunk/stage
#define X_BYTES   8192       // CHUNK_E * 8
#define D_BYTES   4096       // CHUNK_E * 4
#define TOT_BYTES 20480      // x + y + dist
#define STAGE_B   20480
#define SMEM_BUF  1024       // buffers start here; barriers in [0..64)
#define SMEM_DYN  (SMEM_BUF + NSTAGES * STAGE_B)

__device__ float        g_partials[GRID1 * 8];
__device__ unsigned int g_ticket;     // zero-init; last block resets

struct Acc {
    float sm[4];
    unsigned long long cntp;          // 4 x 16-bit packed counts
};

__device__ __forceinline__ uint32_t smem_u32(const void* p) {
    uint32_t a;
    asm("{ .reg .u64 t; cvta.to.shared.u64 t, %1; cvt.u32.u64 %0, t; }"
        : "=r"(a) : "l"(p));
    return a;
}
__device__ __forceinline__ void mbar_init(uint32_t m, uint32_t cnt) {
    asm volatile("mbarrier.init.shared.b64 [%0], %1;" :: "r"(m), "r"(cnt) : "memory");
}
__device__ __forceinline__ void mbar_expect_tx(uint32_t m, uint32_t bytes) {
    asm volatile("mbarrier.arrive.expect_tx.shared.b64 _, [%0], %1;"
                 :: "r"(m), "r"(bytes) : "memory");
}
__device__ __forceinline__ void mbar_arrive(uint32_t m) {
    asm volatile("mbarrier.arrive.shared.b64 _, [%0];" :: "r"(m) : "memory");
}
__device__ __forceinline__ void mbar_wait(uint32_t m, uint32_t ph) {
    asm volatile(
        "{\n\t.reg .pred P1;\n\t"
        "W_%=:\n\t"
        "mbarrier.try_wait.parity.acquire.cta.shared::cta.b64 P1, [%0], %1, 0x989680;\n\t"
        "@P1 bra D_%=;\n\t"
        "bra W_%=;\n\t"
        "D_%=:\n\t}"
        :: "r"(m), "r"(ph) : "memory");
}
__device__ __forceinline__ void bulk_g2s(uint32_t dst, const void* src,
                                         uint32_t bytes, uint32_t mbar) {
    asm volatile(
        "cp.async.bulk.shared::cta.global.mbarrier::complete_tx::bytes [%0], [%1], %2, [%3];"
        :: "r"(dst), "l"(src), "r"(bytes), "r"(mbar) : "memory");
}

__device__ __forceinline__ void elem_acc(Acc& A, float a, float b,
                                         float c, float d, float dv)
{
    float u  = a - c;
    float v  = b - d;
    float d2 = fmaf(u, u, v * v);
    float x2 = fmaf(a, a, b * b);
    float y2 = fmaf(c, c, d * d);
    float p  = fmaxf(x2 * y2, 1e-30f);
    float s  = p * rsqrtf(p);                 // ~sqrt(x2*y2), one MUFU
    float a2 = x2 + y2 - 2.0f * s;            // (|x|-|y|)^2
    float m  = fmaf(0.2f, a2, d2);
    int ib = (int)(dv * 4.0f);
    ib = ib > 3 ? 3 : ib;
    A.cntp += 1ull << (ib << 4);
    #pragma unroll
    for (int bb = 0; bb < 4; bb++)
        if (bb == ib) A.sm[bb] += m;
}

__global__ __launch_bounds__(NTHREADS, 2)
void radial_tma(const float* __restrict__ x,
                const float* __restrict__ y,
                const float* __restrict__ dist,
                int n, float* __restrict__ out)
{
    extern __shared__ __align__(128) char smem[];
    const uint32_t sb  = smem_u32(smem);
    const int      tid = threadIdx.x;
    const int nchunks = n / CHUNK_E;

    // Barriers: full[s] = sb + s*16, empty[s] = sb + s*16 + 8.
    if (tid == 0) {
        #pragma unroll
        for (int s = 0; s < NSTAGES; s++) {
            mbar_init(sb + s * 16,     1);      // full (tx-based)
            mbar_init(sb + s * 16 + 8, NCONS);  // empty
        }
    }
    __syncthreads();

    Acc A;
    A.sm[0] = A.sm[1] = A.sm[2] = A.sm[3] = 0.f;
    A.cntp = 0ull;

    if (tid == NCONS) {
        // -------- producer (one elected thread; runs up to 3 stages ahead) ----
        int s = 0; unsigned ph = 1;            // fresh empties pass parity 1
        const char* xg = (const char*)x;
        const char* yg = (const char*)y;
        const char* dg = (const char*)dist;
        for (int c = blockIdx.x; c < nchunks; c += gridDim.x) {
            uint32_t full  = sb + s * 16;
            uint32_t empty = sb + s * 16 + 8;
            uint32_t buf   = sb + SMEM_BUF + s * STAGE_B;
            mbar_wait(empty, ph);
            mbar_expect_tx(full, TOT_BYTES);
            bulk_g2s(buf,               xg + (size_t)c * X_BYTES, X_BYTES, full);
            bulk_g2s(buf + X_BYTES,     yg + (size_t)c * X_BYTES, X_BYTES, full);
            bulk_g2s(buf + 2 * X_BYTES, dg + (size_t)c * D_BYTES, D_BYTES, full);
            if (++s == NSTAGES) { s = 0; ph ^= 1; }
        }
    } else if (tid < NCONS) {
        // -------- consumers (512 threads; 2 elements each per stage) --------
        int s = 0; unsigned ph = 0;
        for (int c = blockIdx.x; c < nchunks; c += gridDim.x) {
            uint32_t full  = sb + s * 16;
            uint32_t empty = sb + s * 16 + 8;
            char* buf = smem + SMEM_BUF + s * STAGE_B;
            mbar_wait(full, ph);
            const float4* xs  = (const float4*)(buf);
            const float4* ys  = (const float4*)(buf + X_BYTES);
            const float2* dsv = (const float2*)(buf + 2 * X_BYTES);
            float4 xv = xs[tid];
            float4 yv = ys[tid];
            float2 dv = dsv[tid];
            elem_acc(A, xv.x, xv.y, yv.x, yv.y, dv.x);
            elem_acc(A, xv.z, xv.w, yv.z, yv.w, dv.y);
            mbar_arrive(empty);
            if (++s == NSTAGES) { s = 0; ph ^= 1; }
        }
        // Generic tail (n % CHUNK_E) via direct loads — zero for this size.
        if (blockIdx.x == 0) {
            for (int e = nchunks * CHUNK_E + tid; e < n; e += NCONS)
                elem_acc(A, x[2 * e], x[2 * e + 1], y[2 * e], y[2 * e + 1], dist[e]);
        }
    }
    __syncthreads();

    // Block reduction of 8 values (producer warp contributes zeros).
    float v[8];
    #pragma unroll
    for (int b = 0; b < 4; b++) {
        v[b]     = A.sm[b];
        v[4 + b] = (float)((unsigned)(A.cntp >> (b << 4)) & 0xFFFFu);
    }
    __shared__ float shr[NTHREADS / 32][8];
    const int lane = tid & 31;
    const int wid  = tid >> 5;
    #pragma unroll
    for (int k = 0; k < 8; k++) {
        #pragma unroll
        for (int o = 16; o > 0; o >>= 1)
            v[k] += __shfl_down_sync(0xffffffffu, v[k], o);
    }
    if (lane == 0) {
        #pragma unroll
        for (int k = 0; k < 8; k++) shr[wid][k] = v[k];
    }
    __syncthreads();
    if (tid < 8) {
        float s = 0.f;
        #pragma unroll
        for (int w = 0; w < NTHREADS / 32; w++) s += shr[w][tid];
        g_partials[blockIdx.x * 8 + tid] = s;
    }

    // ---- last-block final reduction (threadfence + ticket) ----
    __shared__ int isLast;
    __threadfence();
    if (tid == 0) {
        unsigned t = atomicAdd(&g_ticket, 1u);
        isLast = (t == (unsigned)(gridDim.x - 1));
    }
    __syncthreads();
    if (!isLast) return;

    const int k  = tid & 7;
    const int r0 = tid >> 3;
    float acc = 0.f;
    for (int r = r0; r < GRID1; r += NTHREADS / 8)
        acc += g_partials[r * 8 + k];

    __shared__ float sh2[NTHREADS];
    __shared__ float fin[8];
    sh2[tid] = acc;
    __syncthreads();
    if (tid < 8) {
        float s = 0.f;
        #pragma unroll
        for (int j = 0; j < NTHREADS / 8; j++) s += sh2[j * 8 + tid];
        fin[tid] = s;
    }
    __syncthreads();
    if (tid == 0) {
        float loss = 0.f;
        #pragma unroll
        for (int b = 0; b < 4; b++) {
            float cc = fin[4 + b];
            if (cc > 0.f) loss += fin[b] / (2.0f * cc);
        }
        out[0] = loss;
        g_ticket = 0u;                          // reset for next replay
    }
}

extern "C" void kernel_launch(void* const* d_in, const int* in_sizes, int n_in,
                              void* d_out, int out_size)
{
    const float* x    = (const float*)d_in[0];   // [N,2] f32
    const float* y    = (const float*)d_in[1];   // [N,2] f32
    const float* dist = (const float*)d_in[2];   // [N]   f32
    const int n = in_sizes[2];

    cudaFuncSetAttribute(radial_tma,
                         cudaFuncAttributeMaxDynamicSharedMemorySize, SMEM_DYN);
    radial_tma<<<GRID1, NTHREADS, SMEM_DYN>>>(x, y, dist, n, (float*)d_out);
}

// round 16
// speedup vs baseline: 1.0774x; 1.0097x over previous
#include <cuda_runtime.h>
#include <cstdint>

#define GRID1     296        // 148 SMs * 2 CTAs
#define NCONS     512        // consumer threads
#define NTHREADS  544        // + 1 producer warp
#define NSTAGES   4
#define CHUNK_E   1024       // elements per chunk/stage
#define X_BYTES   8192       // CHUNK_E * 8
#define D_BYTES   4096       // CHUNK_E * 4
#define TOT_BYTES 20480      // x + y + dist
#define STAGE_B   20480
#define SMEM_BUF  1024       // buffers start here; barriers in [0..64)
#define SMEM_DYN  (SMEM_BUF + NSTAGES * STAGE_B)

__device__ float        g_partials[GRID1 * 8];
__device__ unsigned int g_ticket;     // zero-init; last block resets

struct Acc {
    float sm[4];
    unsigned long long cntp;          // 4 x 16-bit packed counts
};

__device__ __forceinline__ uint32_t smem_u32(const void* p) {
    uint32_t a;
    asm("{ .reg .u64 t; cvta.to.shared.u64 t, %1; cvt.u32.u64 %0, t; }"
        : "=r"(a) : "l"(p));
    return a;
}
__device__ __forceinline__ void mbar_init(uint32_t m, uint32_t cnt) {
    asm volatile("mbarrier.init.shared.b64 [%0], %1;" :: "r"(m), "r"(cnt) : "memory");
}
__device__ __forceinline__ void mbar_expect_tx(uint32_t m, uint32_t bytes) {
    asm volatile("mbarrier.arrive.expect_tx.shared.b64 _, [%0], %1;"
                 :: "r"(m), "r"(bytes) : "memory");
}
__device__ __forceinline__ void mbar_arrive(uint32_t m) {
    asm volatile("mbarrier.arrive.shared.b64 _, [%0];" :: "r"(m) : "memory");
}
// Acquire wait — consumers (generic LDS follow the wait).
__device__ __forceinline__ void mbar_wait(uint32_t m, uint32_t ph) {
    asm volatile(
        "{\n\t.reg .pred P1;\n\t"
        "W_%=:\n\t"
        "mbarrier.try_wait.parity.acquire.cta.shared::cta.b64 P1, [%0], %1, 0x989680;\n\t"
        "@P1 bra D_%=;\n\t"
        "bra W_%=;\n\t"
        "D_%=:\n\t}"
        :: "r"(m), "r"(ph) : "memory");
}
// Relaxed wait — producer only: post-wait SMEM accesses are async-proxy
// (expect_tx + cp.async.bulk), ordered by their own fences.
__device__ __forceinline__ void mbar_wait_relaxed(uint32_t m, uint32_t ph) {
    asm volatile(
        "{\n\t.reg .pred P1;\n\t"
        "W_%=:\n\t"
        "mbarrier.try_wait.parity.relaxed.cta.shared::cta.b64 P1, [%0], %1, 0x989680;\n\t"
        "@P1 bra D_%=;\n\t"
        "bra W_%=;\n\t"
        "D_%=:\n\t}"
        :: "r"(m), "r"(ph) : "memory");
}
__device__ __forceinline__ void bulk_g2s(uint32_t dst, const void* src,
                                         uint32_t bytes, uint32_t mbar) {
    asm volatile(
        "cp.async.bulk.shared::cta.global.mbarrier::complete_tx::bytes [%0], [%1], %2, [%3];"
        :: "r"(dst), "l"(src), "r"(bytes), "r"(mbar) : "memory");
}

__device__ __forceinline__ void elem_acc(Acc& A, float a, float b,
                                         float c, float d, float dv)
{
    float u  = a - c;
    float v  = b - d;
    float d2 = fmaf(u, u, v * v);
    float x2 = fmaf(a, a, b * b);
    float y2 = fmaf(c, c, d * d);
    float p  = fmaxf(x2 * y2, 1e-30f);
    float s  = p * rsqrtf(p);                 // ~sqrt(x2*y2), one MUFU
    float a2 = x2 + y2 - 2.0f * s;            // (|x|-|y|)^2
    float m  = fmaf(0.2f, a2, d2);
    int ib = (int)(dv * 4.0f);
    ib = ib > 3 ? 3 : ib;
    A.cntp += 1ull << (ib << 4);
    #pragma unroll
    for (int bb = 0; bb < 4; bb++)
        if (bb == ib) A.sm[bb] += m;
}

__global__ __launch_bounds__(NTHREADS, 2)
void radial_tma(const float* __restrict__ x,
                const float* __restrict__ y,
                const float* __restrict__ dist,
                int n, float* __restrict__ out)
{
    extern __shared__ __align__(128) char smem[];
    const uint32_t sb  = smem_u32(smem);
    const int      tid = threadIdx.x;
    const int nchunks = n / CHUNK_E;

    // Barriers: full[s] = sb + s*16, empty[s] = sb + s*16 + 8.
    if (tid == 0) {
        #pragma unroll
        for (int s = 0; s < NSTAGES; s++) {
            mbar_init(sb + s * 16,     1);      // full (tx-based)
            mbar_init(sb + s * 16 + 8, NCONS);  // empty
        }
    }
    __syncthreads();

    Acc A;
    A.sm[0] = A.sm[1] = A.sm[2] = A.sm[3] = 0.f;
    A.cntp = 0ull;

    if (tid == NCONS) {
        // -------- producer (one elected thread; runs up to 3 stages ahead) ----
        int s = 0; unsigned ph = 1;            // fresh empties pass parity 1
        const char* xg = (const char*)x;
        const char* yg = (const char*)y;
        const char* dg = (const char*)dist;
        for (int c = blockIdx.x; c < nchunks; c += gridDim.x) {
            uint32_t full  = sb + s * 16;
            uint32_t empty = sb + s * 16 + 8;
            uint32_t buf   = sb + SMEM_BUF + s * STAGE_B;
            mbar_wait_relaxed(empty, ph);
            mbar_expect_tx(full, TOT_BYTES);
            bulk_g2s(buf,               xg + (size_t)c * X_BYTES, X_BYTES, full);
            bulk_g2s(buf + X_BYTES,     yg + (size_t)c * X_BYTES, X_BYTES, full);
            bulk_g2s(buf + 2 * X_BYTES, dg + (size_t)c * D_BYTES, D_BYTES, full);
            if (++s == NSTAGES) { s = 0; ph ^= 1; }
        }
    } else if (tid < NCONS) {
        // -------- consumers (512 threads; 2 elements each per stage) --------
        int s = 0; unsigned ph = 0;
        for (int c = blockIdx.x; c < nchunks; c += gridDim.x) {
            uint32_t full  = sb + s * 16;
            uint32_t empty = sb + s * 16 + 8;
            char* buf = smem + SMEM_BUF + s * STAGE_B;
            mbar_wait(full, ph);
            const float4* xs  = (const float4*)(buf);
            const float4* ys  = (const float4*)(buf + X_BYTES);
            const float2* dsv = (const float2*)(buf + 2 * X_BYTES);
            float4 xv = xs[tid];
            float4 yv = ys[tid];
            float2 dv = dsv[tid];
            elem_acc(A, xv.x, xv.y, yv.x, yv.y, dv.x);
            elem_acc(A, xv.z, xv.w, yv.z, yv.w, dv.y);
            mbar_arrive(empty);
            if (++s == NSTAGES) { s = 0; ph ^= 1; }
        }
        // Generic tail (n % CHUNK_E) via direct loads — zero for this size.
        if (blockIdx.x == 0) {
            for (int e = nchunks * CHUNK_E + tid; e < n; e += NCONS)
                elem_acc(A, x[2 * e], x[2 * e + 1], y[2 * e], y[2 * e + 1], dist[e]);
        }
    }
    __syncthreads();

    // Block reduction of 8 values (producer warp contributes zeros).
    float v[8];
    #pragma unroll
    for (int b = 0; b < 4; b++) {
        v[b]     = A.sm[b];
        v[4 + b] = (float)((unsigned)(A.cntp >> (b << 4)) & 0xFFFFu);
    }
    __shared__ float shr[NTHREADS / 32][8];
    const int lane = tid & 31;
    const int wid  = tid >> 5;
    #pragma unroll
    for (int k = 0; k < 8; k++) {
        #pragma unroll
        for (int o = 16; o > 0; o >>= 1)
            v[k] += __shfl_down_sync(0xffffffffu, v[k], o);
    }
    if (lane == 0) {
        #pragma unroll
        for (int k = 0; k < 8; k++) shr[wid][k] = v[k];
    }
    __syncthreads();
    if (tid < 8) {
        float s = 0.f;
        #pragma unroll
        for (int w = 0; w < NTHREADS / 32; w++) s += shr[w][tid];
        g_partials[blockIdx.x * 8 + tid] = s;
    }

    // ---- last-block final reduction (threadfence + ticket) ----
    __shared__ int isLast;
    __threadfence();
    if (tid == 0) {
        unsigned t = atomicAdd(&g_ticket, 1u);
        isLast = (t == (unsigned)(gridDim.x - 1));
    }
    __syncthreads();
    if (!isLast) return;

    const int k  = tid & 7;
    const int r0 = tid >> 3;
    float acc = 0.f;
    for (int r = r0; r < GRID1; r += NTHREADS / 8)
        acc += g_partials[r * 8 + k];

    __shared__ float sh2[NTHREADS];
    __shared__ float fin[8];
    sh2[tid] = acc;
    __syncthreads();
    if (tid < 8) {
        float s = 0.f;
        #pragma unroll
        for (int j = 0; j < NTHREADS / 8; j++) s += sh2[j * 8 + tid];
        fin[tid] = s;
    }
    __syncthreads();
    if (tid == 0) {
        float loss = 0.f;
        #pragma unroll
        for (int b = 0; b < 4; b++) {
            float cc = fin[4 + b];
            if (cc > 0.f) loss += fin[b] / (2.0f * cc);
        }
        out[0] = loss;
        g_ticket = 0u;                          // reset for next replay
    }
}

extern "C" void kernel_launch(void* const* d_in, const int* in_sizes, int n_in,
                              void* d_out, int out_size)
{
    const float* x    = (const float*)d_in[0];   // [N,2] f32
    const float* y    = (const float*)d_in[1];   // [N,2] f32
    const float* dist = (const float*)d_in[2];   // [N]   f32
    const int n = in_sizes[2];

    cudaFuncSetAttribute(radial_tma,
                         cudaFuncAttributeMaxDynamicSharedMemorySize, SMEM_DYN);
    radial_tma<<<GRID1, NTHREADS, SMEM_DYN>>>(x, y, dist, n, (float*)d_out);
}